// round 2
// baseline (speedup 1.0000x reference)
#include <cuda_runtime.h>
#include <cstdint>
#include <cstddef>

// ---------------------------------------------------------------------------
// Problem constants (fixed by the dataset)
// ---------------------------------------------------------------------------
#define N_NODES 50000
#define N_EDGES 1600000
#define NFEAT   512
#define NHID    64
#define H1      8
#define NCLASS  16
#define HCAT    (H1 * NHID)   // 512
#define ALPHA   0.2f

typedef unsigned long long u64;

// f32x2 packed FMA (sm_100+): d = a*b + c on two packed floats, rn rounding
// identical to two scalar fmaf's.
__device__ __forceinline__ u64 fma2(u64 a, u64 b, u64 c) {
    u64 d;
    asm("fma.rn.f32x2 %0, %1, %2, %3;" : "=l"(d) : "l"(a), "l"(b), "l"(c));
    return d;
}
__device__ __forceinline__ u64 packdup(float v) {
    u64 d;
    asm("mov.b64 %0, {%1, %1};" : "=l"(d) : "f"(v));
    return d;
}
union F2U { u64 u; float2 f; };

// ---------------------------------------------------------------------------
// Scratch (device globals; no allocation allowed)
// ---------------------------------------------------------------------------
__device__ float g_h1[(size_t)H1 * N_NODES * NHID];     // per-head layer1 features
__device__ float g_hcat[(size_t)N_NODES * HCAT];        // concat(elu(h_prime1))
__device__ float g_h2[(size_t)N_NODES * NCLASS];        // layer2 linear
__device__ float g_p2[(size_t)N_NODES * NCLASS];        // layer2 aggregated
__device__ float g_s1src[H1 * N_NODES];
__device__ float g_s1dst[H1 * N_NODES];
__device__ float g_s2src[N_NODES];
__device__ float g_s2dst[N_NODES];
__device__ int   g_deg[N_NODES];
__device__ int   g_rowptr[N_NODES + 1];
__device__ int   g_fill[N_NODES];
__device__ int   g_dst_sorted[N_EDGES];

// ---------------------------------------------------------------------------
// CSR construction
// ---------------------------------------------------------------------------
__global__ void k_zero_deg() {
    int i = blockIdx.x * blockDim.x + threadIdx.x;
    if (i < N_NODES) g_deg[i] = 0;
}

__global__ void k_degree(const int* __restrict__ ei) {
    int e = blockIdx.x * blockDim.x + threadIdx.x;
    if (e < N_EDGES) atomicAdd(&g_deg[ei[e]], 1);
}

// Single-block exclusive scan over 50000 degrees -> rowptr, fill
__global__ __launch_bounds__(1024) void k_scan() {
    __shared__ int sums[1024];
    int tid = threadIdx.x;
    constexpr int CH = (N_NODES + 1023) / 1024;  // 49
    int start = tid * CH;
    int end = min(start + CH, N_NODES);
    int s = 0;
    for (int i = start; i < end; ++i) s += g_deg[i];
    sums[tid] = s;
    __syncthreads();
    for (int off = 1; off < 1024; off <<= 1) {
        int t = (tid >= off) ? sums[tid - off] : 0;
        __syncthreads();
        sums[tid] += t;
        __syncthreads();
    }
    int running = sums[tid] - s;  // exclusive prefix of this chunk
    for (int i = start; i < end; ++i) {
        g_rowptr[i] = running;
        g_fill[i]   = running;
        running += g_deg[i];
    }
    if (tid == 1023) g_rowptr[N_NODES] = sums[1023];
}

__global__ void k_scatter(const int* __restrict__ ei) {
    int e = blockIdx.x * blockDim.x + threadIdx.x;
    if (e < N_EDGES) {
        int s = ei[e];
        int d = ei[N_EDGES + e];
        int pos = atomicAdd(&g_fill[s], 1);
        g_dst_sorted[pos] = d;
    }
}

// ---------------------------------------------------------------------------
// Layer-1 GEMM, f32x2 packed-FMA version.
// C[h][M, 64] = A[M, 512] @ W1[h][512, 64]
// BM=128, BN=64, BK=16, 256 threads, 8Mx4N microtile as 4 Mpairs x 4 N
// in f32x2 accumulators. B tile stored duplicated (b,b) so the inner loop
// is pure LDS.128 + fma.rn.f32x2.
// ---------------------------------------------------------------------------
__global__ __launch_bounds__(256) void k_gemm1(
    const float* __restrict__ A, const float* __restrict__ Wbase,
    float* __restrict__ Cbase)
{
    constexpr int BM = 128, BN = 64, BK = 16, K = NFEAT;
    __shared__ float As[BK][BM];   // transposed A tile: [k][m], m contiguous
    __shared__ u64   Bs[BK][BN];   // duplicated B: (b,b) pairs

    int h = blockIdx.y;
    const float* B = Wbase + (size_t)h * K * BN;
    float* C = Cbase + (size_t)h * N_NODES * BN;

    int m0 = blockIdx.x * BM;
    int tid = threadIdx.x;
    int tx = tid & 15;          // N quad: cols tx*4..tx*4+3
    int ty = tid >> 4;          // M oct:  rows ty*8..ty*8+7

    int aRow = tid >> 1;            // 0..127
    int aCol = (tid & 1) * 8;       // 0 or 8
    int bRow = tid >> 4;            // 0..15
    int bCol = (tid & 15) * 4;      // 0..60

    const bool aValid = (m0 + aRow) < N_NODES;
    const float* Aptr = A + (size_t)(m0 + aRow) * K + aCol;
    const float* Bptr = B + (size_t)bRow * BN + bCol;

    u64 acc[4][4];
#pragma unroll
    for (int i = 0; i < 4; ++i)
#pragma unroll
        for (int j = 0; j < 4; ++j) acc[i][j] = 0ull;

    for (int k0 = 0; k0 < K; k0 += BK) {
        float4 a0 = make_float4(0.f, 0.f, 0.f, 0.f), a1 = a0;
        if (aValid) {
            a0 = *(const float4*)(Aptr + k0);
            a1 = *(const float4*)(Aptr + k0 + 4);
        }
        float4 b4 = *(const float4*)(Bptr + (size_t)k0 * BN);
        __syncthreads();
        As[aCol + 0][aRow] = a0.x;
        As[aCol + 1][aRow] = a0.y;
        As[aCol + 2][aRow] = a0.z;
        As[aCol + 3][aRow] = a0.w;
        As[aCol + 4][aRow] = a1.x;
        As[aCol + 5][aRow] = a1.y;
        As[aCol + 6][aRow] = a1.z;
        As[aCol + 7][aRow] = a1.w;
        Bs[bRow][bCol + 0] = packdup(b4.x);
        Bs[bRow][bCol + 1] = packdup(b4.y);
        Bs[bRow][bCol + 2] = packdup(b4.z);
        Bs[bRow][bCol + 3] = packdup(b4.w);
        __syncthreads();
#pragma unroll
        for (int k = 0; k < BK; ++k) {
            const u64* ap = (const u64*)&As[k][ty * 8];
            const u64* bp = &Bs[k][tx * 4];
            u64 A0 = ap[0], A1 = ap[1], A2 = ap[2], A3 = ap[3];
            u64 B0 = bp[0], B1 = bp[1], B2 = bp[2], B3 = bp[3];
            acc[0][0] = fma2(A0, B0, acc[0][0]);
            acc[0][1] = fma2(A0, B1, acc[0][1]);
            acc[0][2] = fma2(A0, B2, acc[0][2]);
            acc[0][3] = fma2(A0, B3, acc[0][3]);
            acc[1][0] = fma2(A1, B0, acc[1][0]);
            acc[1][1] = fma2(A1, B1, acc[1][1]);
            acc[1][2] = fma2(A1, B2, acc[1][2]);
            acc[1][3] = fma2(A1, B3, acc[1][3]);
            acc[2][0] = fma2(A2, B0, acc[2][0]);
            acc[2][1] = fma2(A2, B1, acc[2][1]);
            acc[2][2] = fma2(A2, B2, acc[2][2]);
            acc[2][3] = fma2(A2, B3, acc[2][3]);
            acc[3][0] = fma2(A3, B0, acc[3][0]);
            acc[3][1] = fma2(A3, B1, acc[3][1]);
            acc[3][2] = fma2(A3, B2, acc[3][2]);
            acc[3][3] = fma2(A3, B3, acc[3][3]);
        }
    }

    // Epilogue: acc[mp][j] = (row 2mp sum, row 2mp+1 sum) for col tx*4+j
#pragma unroll
    for (int mp = 0; mp < 4; ++mp) {
        int r0 = m0 + ty * 8 + mp * 2;
        F2U u0, u1, u2, u3;
        u0.u = acc[mp][0]; u1.u = acc[mp][1]; u2.u = acc[mp][2]; u3.u = acc[mp][3];
        if (r0 < N_NODES)
            *(float4*)&C[(size_t)r0 * BN + tx * 4] =
                make_float4(u0.f.x, u1.f.x, u2.f.x, u3.f.x);
        if (r0 + 1 < N_NODES)
            *(float4*)&C[(size_t)(r0 + 1) * BN + tx * 4] =
                make_float4(u0.f.y, u1.f.y, u2.f.y, u3.f.y);
    }
}

// ---------------------------------------------------------------------------
// Generic tiled SGEMM (used for layer 2): C[M,ncols] = A[M,K] @ B[K,ncols]
// ---------------------------------------------------------------------------
__global__ __launch_bounds__(256) void k_sgemm(
    const float* __restrict__ A, const float* __restrict__ Bbase,
    float* __restrict__ Cbase, int M, int K, int ncols,
    long bHeadStride, long cHeadStride)
{
    constexpr int BM = 64, BN = 64, BK = 16;
    __shared__ float As[BK][BM];   // transposed A tile
    __shared__ float Bsh[BK][BN];

    int h = blockIdx.y;
    const float* B = Bbase + (size_t)h * bHeadStride;
    float* C = Cbase + (size_t)h * cHeadStride;

    int m0 = blockIdx.x * BM;
    int tid = threadIdx.x;
    int tx = tid & 15, ty = tid >> 4;

    float acc[4][4] = {};

    int aRow = tid >> 2;          // 0..63
    int aCol = (tid & 3) * 4;     // 0,4,8,12
    int bRow = tid >> 4;          // 0..15
    int bCol = (tid & 15) * 4;    // 0..60

    const bool aValid = (m0 + aRow) < M;
    const bool bValid = bCol < ncols;
    const float* Aptr = A + (size_t)(m0 + aRow) * K + aCol;
    const float* Bptr = B + (size_t)bRow * ncols + bCol;

    for (int k0 = 0; k0 < K; k0 += BK) {
        float4 av = aValid ? *(const float4*)(Aptr + k0) : make_float4(0.f, 0.f, 0.f, 0.f);
        float4 bv = bValid ? *(const float4*)(Bptr + (size_t)k0 * ncols) : make_float4(0.f, 0.f, 0.f, 0.f);
        __syncthreads();
        As[aCol + 0][aRow] = av.x;
        As[aCol + 1][aRow] = av.y;
        As[aCol + 2][aRow] = av.z;
        As[aCol + 3][aRow] = av.w;
        *(float4*)&Bsh[bRow][bCol] = bv;
        __syncthreads();
#pragma unroll
        for (int k = 0; k < BK; ++k) {
            float4 a4 = *(const float4*)&As[k][ty * 4];
            float4 b4 = *(const float4*)&Bsh[k][tx * 4];
            float ar[4] = {a4.x, a4.y, a4.z, a4.w};
            float br[4] = {b4.x, b4.y, b4.z, b4.w};
#pragma unroll
            for (int i = 0; i < 4; ++i)
#pragma unroll
                for (int j = 0; j < 4; ++j)
                    acc[i][j] = fmaf(ar[i], br[j], acc[i][j]);
        }
    }

#pragma unroll
    for (int i = 0; i < 4; ++i) {
        int r = m0 + ty * 4 + i;
        if (r >= M) break;
#pragma unroll
        for (int j = 0; j < 4; ++j) {
            int c = tx * 4 + j;
            if (c < ncols) C[(size_t)r * ncols + c] = acc[i][j];
        }
    }
}

// ---------------------------------------------------------------------------
// Layer-1 attention scores: s_src/s_dst = h1 . a1 parts, warp per (node, head)
// ---------------------------------------------------------------------------
__global__ __launch_bounds__(256) void k_scores1(const float* __restrict__ a1) {
    int warp = threadIdx.x >> 5;
    int lane = threadIdx.x & 31;
    int n = blockIdx.x * 8 + warp;
    int h = blockIdx.y;
    if (n >= N_NODES) return;
    const float* hp = g_h1 + ((size_t)h * N_NODES + n) * NHID;
    float2 hv = *(const float2*)(hp + lane * 2);
    const float* a = a1 + h * (2 * NHID);
    float2 as = *(const float2*)(a + lane * 2);
    float2 ad = *(const float2*)(a + NHID + lane * 2);
    float ps = hv.x * as.x + hv.y * as.y;
    float pd = hv.x * ad.x + hv.y * ad.y;
#pragma unroll
    for (int o = 16; o; o >>= 1) {
        ps += __shfl_xor_sync(0xFFFFFFFFu, ps, o);
        pd += __shfl_xor_sync(0xFFFFFFFFu, pd, o);
    }
    if (lane == 0) {
        g_s1src[h * N_NODES + n] = ps;
        g_s1dst[h * N_NODES + n] = pd;
    }
}

// ---------------------------------------------------------------------------
// Layer-1 CSR aggregation: warp per (node, head); lane holds 2 features.
// Writes elu(agg/rowsum) straight into hcat[n][h*64 + f].
// ---------------------------------------------------------------------------
__global__ __launch_bounds__(256) void k_agg1() {
    int warp = threadIdx.x >> 5;
    int lane = threadIdx.x & 31;
    int n = blockIdx.x * 8 + warp;
    int h = blockIdx.y;
    if (n >= N_NODES) return;
    int beg = g_rowptr[n], end = g_rowptr[n + 1];
    float ssrc = g_s1src[h * N_NODES + n];
    const float* hb = g_h1 + (size_t)h * N_NODES * NHID;
    const float* sd = g_s1dst + (size_t)h * N_NODES;
    float ax = 0.f, ay = 0.f, rs = 0.f;
    for (int i = beg; i < end; ++i) {
        int v = __ldg(&g_dst_sorted[i]);
        float lg = ssrc + __ldg(&sd[v]);
        lg = lg > 0.f ? lg : ALPHA * lg;
        float e = __expf(-lg);
        rs += e;
        float2 hv = *(const float2*)(hb + (size_t)v * NHID + lane * 2);
        ax = fmaf(e, hv.x, ax);
        ay = fmaf(e, hv.y, ay);
    }
    float inv = 1.f / rs;
    float o0 = ax * inv, o1 = ay * inv;
    o0 = o0 > 0.f ? o0 : expm1f(o0);
    o1 = o1 > 0.f ? o1 : expm1f(o1);
    *(float2*)(g_hcat + (size_t)n * HCAT + h * NHID + lane * 2) = make_float2(o0, o1);
}

// ---------------------------------------------------------------------------
// Layer-2 scores (16-dim dots, thread per node)
// ---------------------------------------------------------------------------
__global__ void k_scores2(const float* __restrict__ a2) {
    int n = blockIdx.x * blockDim.x + threadIdx.x;
    if (n >= N_NODES) return;
    float ps = 0.f, pd = 0.f;
    const float* hp = g_h2 + (size_t)n * NCLASS;
#pragma unroll
    for (int c = 0; c < NCLASS; ++c) {
        float v = hp[c];
        ps = fmaf(v, __ldg(&a2[c]), ps);
        pd = fmaf(v, __ldg(&a2[NCLASS + c]), pd);
    }
    g_s2src[n] = ps;
    g_s2dst[n] = pd;
}

// ---------------------------------------------------------------------------
// Layer-2 CSR aggregation: thread per (node, class); 2 nodes per warp.
// ---------------------------------------------------------------------------
__global__ __launch_bounds__(256) void k_agg2() {
    int t = blockIdx.x * blockDim.x + threadIdx.x;
    int n = t >> 4;
    int f = t & 15;
    if (n >= N_NODES) return;
    int beg = g_rowptr[n], end = g_rowptr[n + 1];
    float ss = g_s2src[n];
    float acc = 0.f, rs = 0.f;
    for (int i = beg; i < end; ++i) {
        int v = __ldg(&g_dst_sorted[i]);
        float lg = ss + __ldg(&g_s2dst[v]);
        lg = lg > 0.f ? lg : ALPHA * lg;
        float e = __expf(-lg);
        rs += e;
        acc = fmaf(e, __ldg(&g_h2[(size_t)v * NCLASS + f]), acc);
    }
    g_p2[(size_t)n * NCLASS + f] = acc / rs;
}

// ---------------------------------------------------------------------------
// elu + log_softmax over 16 classes, thread per node
// ---------------------------------------------------------------------------
__global__ void k_final(float* __restrict__ out) {
    int n = blockIdx.x * blockDim.x + threadIdx.x;
    if (n >= N_NODES) return;
    float v[NCLASS];
    float m = -1e30f;
#pragma unroll
    for (int c = 0; c < NCLASS; ++c) {
        float x = g_p2[(size_t)n * NCLASS + c];
        x = x > 0.f ? x : expm1f(x);
        v[c] = x;
        m = fmaxf(m, x);
    }
    float s = 0.f;
#pragma unroll
    for (int c = 0; c < NCLASS; ++c) s += __expf(v[c] - m);
    float l = m + logf(s);
#pragma unroll
    for (int c = 0; c < NCLASS; ++c) out[(size_t)n * NCLASS + c] = v[c] - l;
}

// ---------------------------------------------------------------------------
// Launch
// ---------------------------------------------------------------------------
extern "C" void kernel_launch(void* const* d_in, const int* in_sizes, int n_in,
                              void* d_out, int out_size) {
    const float* x  = (const float*)d_in[0];
    const int*   ei = (const int*)d_in[1];
    const float* W1 = (const float*)d_in[2];
    const float* a1 = (const float*)d_in[3];
    const float* W2 = (const float*)d_in[4];
    const float* a2 = (const float*)d_in[5];
    float* out = (float*)d_out;

    void *h1p = nullptr, *hcatp = nullptr, *h2p = nullptr;
    cudaGetSymbolAddress(&h1p, g_h1);
    cudaGetSymbolAddress(&hcatp, g_hcat);
    cudaGetSymbolAddress(&h2p, g_h2);

    // CSR build
    k_zero_deg<<<(N_NODES + 255) / 256, 256>>>();
    k_degree<<<(N_EDGES + 255) / 256, 256>>>(ei);
    k_scan<<<1, 1024>>>();
    k_scatter<<<(N_EDGES + 255) / 256, 256>>>(ei);

    // Layer 1: packed-f32x2 GEMM
    dim3 g1((N_NODES + 127) / 128, H1);
    k_gemm1<<<g1, 256>>>(x, W1, (float*)h1p);
    dim3 gw((N_NODES + 7) / 8, H1);
    k_scores1<<<gw, 256>>>(a1);
    k_agg1<<<gw, 256>>>();

    // Layer 2
    dim3 g2((N_NODES + 63) / 64, 1);
    k_sgemm<<<g2, 256>>>((const float*)hcatp, W2, (float*)h2p, N_NODES, HCAT, NCLASS, 0, 0);
    k_scores2<<<(N_NODES + 255) / 256, 256>>>(a2);
    k_agg2<<<(N_NODES * NCLASS + 255) / 256, 256>>>();
    k_final<<<(N_NODES + 255) / 256, 256>>>(out);
}

// round 3
// speedup vs baseline: 1.8438x; 1.8438x over previous
#include <cuda_runtime.h>
#include <cstdint>
#include <cstddef>

// ---------------------------------------------------------------------------
// Problem constants (fixed by the dataset)
// ---------------------------------------------------------------------------
#define N_NODES 50000
#define N_EDGES 1600000
#define NFEAT   512
#define NHID    64
#define H1      8
#define NCLASS  16
#define HCAT    (H1 * NHID)   // 512
#define ALPHA   0.2f

// ---------------------------------------------------------------------------
// Scratch (device globals; no allocation allowed)
// ---------------------------------------------------------------------------
__device__ float g_h1[(size_t)H1 * N_NODES * NHID];     // per-head layer1 features
__device__ float g_hcat[(size_t)N_NODES * HCAT];        // concat(elu(h_prime1))
__device__ float g_h2[(size_t)N_NODES * NCLASS];        // layer2 linear
__device__ float g_p2[(size_t)N_NODES * NCLASS];        // layer2 aggregated
__device__ float g_s1src[H1 * N_NODES];
__device__ float g_s1dst[H1 * N_NODES];
__device__ float g_s2src[N_NODES];
__device__ float g_s2dst[N_NODES];
__device__ int   g_deg[N_NODES];
__device__ int   g_rowptr[N_NODES + 1];
__device__ int   g_fill[N_NODES];
__device__ int   g_dst_sorted[N_EDGES];

// ---------------------------------------------------------------------------
// tf32 helpers
// ---------------------------------------------------------------------------
__device__ __forceinline__ uint32_t f2tf32(float x) {
    uint32_t r;
    asm("cvt.rna.tf32.f32 %0, %1;" : "=r"(r) : "f"(x));
    return r;
}

__device__ __forceinline__ void mma_tf32(float4& d,
                                         const uint32_t a0, const uint32_t a1,
                                         const uint32_t a2, const uint32_t a3,
                                         const uint32_t b0, const uint32_t b1) {
    asm volatile(
        "mma.sync.aligned.m16n8k8.row.col.f32.tf32.tf32.f32 "
        "{%0,%1,%2,%3}, {%4,%5,%6,%7}, {%8,%9}, {%0,%1,%2,%3};"
        : "+f"(d.x), "+f"(d.y), "+f"(d.z), "+f"(d.w)
        : "r"(a0), "r"(a1), "r"(a2), "r"(a3), "r"(b0), "r"(b1));
}

// ---------------------------------------------------------------------------
// CSR construction
// ---------------------------------------------------------------------------
__global__ void k_zero_deg() {
    int i = blockIdx.x * blockDim.x + threadIdx.x;
    if (i < N_NODES) g_deg[i] = 0;
}

__global__ void k_degree(const int* __restrict__ ei) {
    int e = blockIdx.x * blockDim.x + threadIdx.x;
    if (e < N_EDGES) atomicAdd(&g_deg[ei[e]], 1);
}

// Single-block exclusive scan over 50000 degrees -> rowptr, fill
__global__ __launch_bounds__(1024) void k_scan() {
    __shared__ int sums[1024];
    int tid = threadIdx.x;
    constexpr int CH = (N_NODES + 1023) / 1024;  // 49
    int start = tid * CH;
    int end = min(start + CH, N_NODES);
    int s = 0;
    for (int i = start; i < end; ++i) s += g_deg[i];
    sums[tid] = s;
    __syncthreads();
    for (int off = 1; off < 1024; off <<= 1) {
        int t = (tid >= off) ? sums[tid - off] : 0;
        __syncthreads();
        sums[tid] += t;
        __syncthreads();
    }
    int running = sums[tid] - s;  // exclusive prefix of this chunk
    for (int i = start; i < end; ++i) {
        g_rowptr[i] = running;
        g_fill[i]   = running;
        running += g_deg[i];
    }
    if (tid == 1023) g_rowptr[N_NODES] = sums[1023];
}

__global__ void k_scatter(const int* __restrict__ ei) {
    int e = blockIdx.x * blockDim.x + threadIdx.x;
    if (e < N_EDGES) {
        int s = ei[e];
        int d = ei[N_EDGES + e];
        int pos = atomicAdd(&g_fill[s], 1);
        g_dst_sorted[pos] = d;
    }
}

// ---------------------------------------------------------------------------
// Layer-1 GEMM via tf32 tensor-core mma.sync.
// C[h][M, 64] = A[M, 512] @ W1[h][512, 64]
// Block tile 128x64x16, 256 threads = 8 warps in 4(m) x 2(n) grid,
// 32x32 per warp = 2(m) x 4(n) m16n8k8 subtiles.
// Smem padded: As stride 20, Bs stride 72 (conflict-free fragment loads).
// ---------------------------------------------------------------------------
#define AS_STRIDE 20
#define BS_STRIDE 72

__global__ __launch_bounds__(256) void k_gemm1(
    const float* __restrict__ A, const float* __restrict__ Wbase,
    float* __restrict__ Cbase)
{
    constexpr int BM = 128, BK = 16, K = NFEAT, BN = 64;
    __shared__ uint32_t As[BM * AS_STRIDE];   // tf32 bits, [m][k]
    __shared__ uint32_t Bs[BK * BS_STRIDE];   // tf32 bits, [k][n]

    int h = blockIdx.y;
    const float* B = Wbase + (size_t)h * K * BN;
    float* C = Cbase + (size_t)h * N_NODES * BN;

    int m0 = blockIdx.x * BM;
    int tid = threadIdx.x;
    int warp = tid >> 5;
    int lane = tid & 31;
    int g = lane >> 2;        // groupID 0..7
    int t = lane & 3;         // thread-in-group 0..3
    int wm = warp >> 1;       // 0..3 -> m offset wm*32
    int wn = warp & 1;        // 0..1 -> n offset wn*32

    // Global load assignments
    int aRow = tid >> 1;           // 0..127
    int aCol = (tid & 1) * 8;      // 0 or 8
    int bRow = tid >> 4;           // 0..15
    int bCol = (tid & 15) * 4;     // 0..60
    const bool aValid = (m0 + aRow) < N_NODES;
    const float* Aptr = A + (size_t)(m0 + aRow) * K + aCol;
    const float* Bptr = B + (size_t)bRow * BN + bCol;

    float4 acc[2][4];
#pragma unroll
    for (int mi = 0; mi < 2; ++mi)
#pragma unroll
        for (int nj = 0; nj < 4; ++nj)
            acc[mi][nj] = make_float4(0.f, 0.f, 0.f, 0.f);

    for (int k0 = 0; k0 < K; k0 += BK) {
        float4 a0 = make_float4(0.f, 0.f, 0.f, 0.f), a1 = a0;
        if (aValid) {
            a0 = *(const float4*)(Aptr + k0);
            a1 = *(const float4*)(Aptr + k0 + 4);
        }
        float4 b4 = *(const float4*)(Bptr + (size_t)k0 * BN);
        __syncthreads();
        uint32_t* ar = &As[aRow * AS_STRIDE + aCol];
        ar[0] = f2tf32(a0.x); ar[1] = f2tf32(a0.y);
        ar[2] = f2tf32(a0.z); ar[3] = f2tf32(a0.w);
        ar[4] = f2tf32(a1.x); ar[5] = f2tf32(a1.y);
        ar[6] = f2tf32(a1.z); ar[7] = f2tf32(a1.w);
        uint32_t* br = &Bs[bRow * BS_STRIDE + bCol];
        br[0] = f2tf32(b4.x); br[1] = f2tf32(b4.y);
        br[2] = f2tf32(b4.z); br[3] = f2tf32(b4.w);
        __syncthreads();

#pragma unroll
        for (int kk = 0; kk < BK; kk += 8) {
            uint32_t af[2][4];
#pragma unroll
            for (int mi = 0; mi < 2; ++mi) {
                int r = wm * 32 + mi * 16 + g;
                af[mi][0] = As[r * AS_STRIDE + kk + t];
                af[mi][1] = As[(r + 8) * AS_STRIDE + kk + t];
                af[mi][2] = As[r * AS_STRIDE + kk + t + 4];
                af[mi][3] = As[(r + 8) * AS_STRIDE + kk + t + 4];
            }
            uint32_t bf[4][2];
#pragma unroll
            for (int nj = 0; nj < 4; ++nj) {
                int c = wn * 32 + nj * 8 + g;
                bf[nj][0] = Bs[(kk + t) * BS_STRIDE + c];
                bf[nj][1] = Bs[(kk + t + 4) * BS_STRIDE + c];
            }
#pragma unroll
            for (int mi = 0; mi < 2; ++mi)
#pragma unroll
                for (int nj = 0; nj < 4; ++nj)
                    mma_tf32(acc[mi][nj],
                             af[mi][0], af[mi][1], af[mi][2], af[mi][3],
                             bf[nj][0], bf[nj][1]);
        }
    }

    // Epilogue: c0,c1 -> [row g][col 2t, 2t+1]; c2,c3 -> row g+8
#pragma unroll
    for (int mi = 0; mi < 2; ++mi) {
#pragma unroll
        for (int nj = 0; nj < 4; ++nj) {
            int r = m0 + wm * 32 + mi * 16 + g;
            int c = wn * 32 + nj * 8 + t * 2;
            float4 v = acc[mi][nj];
            if (r < N_NODES)
                *(float2*)&C[(size_t)r * BN + c] = make_float2(v.x, v.y);
            if (r + 8 < N_NODES)
                *(float2*)&C[(size_t)(r + 8) * BN + c] = make_float2(v.z, v.w);
        }
    }
}

// ---------------------------------------------------------------------------
// Generic tiled SGEMM (used for layer 2): C[M,ncols] = A[M,K] @ B[K,ncols]
// ---------------------------------------------------------------------------
__global__ __launch_bounds__(256) void k_sgemm(
    const float* __restrict__ A, const float* __restrict__ Bbase,
    float* __restrict__ Cbase, int M, int K, int ncols,
    long bHeadStride, long cHeadStride)
{
    constexpr int BM = 64, BN = 64, BK = 16;
    __shared__ float As[BK][BM];   // transposed A tile
    __shared__ float Bsh[BK][BN];

    int h = blockIdx.y;
    const float* B = Bbase + (size_t)h * bHeadStride;
    float* C = Cbase + (size_t)h * cHeadStride;

    int m0 = blockIdx.x * BM;
    int tid = threadIdx.x;
    int tx = tid & 15, ty = tid >> 4;

    float acc[4][4] = {};

    int aRow = tid >> 2;          // 0..63
    int aCol = (tid & 3) * 4;     // 0,4,8,12
    int bRow = tid >> 4;          // 0..15
    int bCol = (tid & 15) * 4;    // 0..60

    const bool aValid = (m0 + aRow) < M;
    const bool bValid = bCol < ncols;
    const float* Aptr = A + (size_t)(m0 + aRow) * K + aCol;
    const float* Bptr = B + (size_t)bRow * ncols + bCol;

    for (int k0 = 0; k0 < K; k0 += BK) {
        float4 av = aValid ? *(const float4*)(Aptr + k0) : make_float4(0.f, 0.f, 0.f, 0.f);
        float4 bv = bValid ? *(const float4*)(Bptr + (size_t)k0 * ncols) : make_float4(0.f, 0.f, 0.f, 0.f);
        __syncthreads();
        As[aCol + 0][aRow] = av.x;
        As[aCol + 1][aRow] = av.y;
        As[aCol + 2][aRow] = av.z;
        As[aCol + 3][aRow] = av.w;
        *(float4*)&Bsh[bRow][bCol] = bv;
        __syncthreads();
#pragma unroll
        for (int k = 0; k < BK; ++k) {
            float4 a4 = *(const float4*)&As[k][ty * 4];
            float4 b4 = *(const float4*)&Bsh[k][tx * 4];
            float ar[4] = {a4.x, a4.y, a4.z, a4.w};
            float br[4] = {b4.x, b4.y, b4.z, b4.w};
#pragma unroll
            for (int i = 0; i < 4; ++i)
#pragma unroll
                for (int j = 0; j < 4; ++j)
                    acc[i][j] = fmaf(ar[i], br[j], acc[i][j]);
        }
    }

#pragma unroll
    for (int i = 0; i < 4; ++i) {
        int r = m0 + ty * 4 + i;
        if (r >= M) break;
#pragma unroll
        for (int j = 0; j < 4; ++j) {
            int c = tx * 4 + j;
            if (c < ncols) C[(size_t)r * ncols + c] = acc[i][j];
        }
    }
}

// ---------------------------------------------------------------------------
// Layer-1 attention scores: s_src/s_dst = h1 . a1 parts, warp per (node, head)
// ---------------------------------------------------------------------------
__global__ __launch_bounds__(256) void k_scores1(const float* __restrict__ a1) {
    int warp = threadIdx.x >> 5;
    int lane = threadIdx.x & 31;
    int n = blockIdx.x * 8 + warp;
    int h = blockIdx.y;
    if (n >= N_NODES) return;
    const float* hp = g_h1 + ((size_t)h * N_NODES + n) * NHID;
    float2 hv = *(const float2*)(hp + lane * 2);
    const float* a = a1 + h * (2 * NHID);
    float2 as = *(const float2*)(a + lane * 2);
    float2 ad = *(const float2*)(a + NHID + lane * 2);
    float ps = hv.x * as.x + hv.y * as.y;
    float pd = hv.x * ad.x + hv.y * ad.y;
#pragma unroll
    for (int o = 16; o; o >>= 1) {
        ps += __shfl_xor_sync(0xFFFFFFFFu, ps, o);
        pd += __shfl_xor_sync(0xFFFFFFFFu, pd, o);
    }
    if (lane == 0) {
        g_s1src[h * N_NODES + n] = ps;
        g_s1dst[h * N_NODES + n] = pd;
    }
}

// ---------------------------------------------------------------------------
// Layer-1 CSR aggregation: warp per (node, head); lane holds 2 features.
// Writes elu(agg/rowsum) straight into hcat[n][h*64 + f].
// ---------------------------------------------------------------------------
__global__ __launch_bounds__(256) void k_agg1() {
    int warp = threadIdx.x >> 5;
    int lane = threadIdx.x & 31;
    int n = blockIdx.x * 8 + warp;
    int h = blockIdx.y;
    if (n >= N_NODES) return;
    int beg = g_rowptr[n], end = g_rowptr[n + 1];
    float ssrc = g_s1src[h * N_NODES + n];
    const float* hb = g_h1 + (size_t)h * N_NODES * NHID;
    const float* sd = g_s1dst + (size_t)h * N_NODES;
    float ax = 0.f, ay = 0.f, rs = 0.f;
    for (int i = beg; i < end; ++i) {
        int v = __ldg(&g_dst_sorted[i]);
        float lg = ssrc + __ldg(&sd[v]);
        lg = lg > 0.f ? lg : ALPHA * lg;
        float e = __expf(-lg);
        rs += e;
        float2 hv = *(const float2*)(hb + (size_t)v * NHID + lane * 2);
        ax = fmaf(e, hv.x, ax);
        ay = fmaf(e, hv.y, ay);
    }
    float inv = 1.f / rs;
    float o0 = ax * inv, o1 = ay * inv;
    o0 = o0 > 0.f ? o0 : expm1f(o0);
    o1 = o1 > 0.f ? o1 : expm1f(o1);
    *(float2*)(g_hcat + (size_t)n * HCAT + h * NHID + lane * 2) = make_float2(o0, o1);
}

// ---------------------------------------------------------------------------
// Layer-2 scores (16-dim dots, thread per node)
// ---------------------------------------------------------------------------
__global__ void k_scores2(const float* __restrict__ a2) {
    int n = blockIdx.x * blockDim.x + threadIdx.x;
    if (n >= N_NODES) return;
    float ps = 0.f, pd = 0.f;
    const float* hp = g_h2 + (size_t)n * NCLASS;
#pragma unroll
    for (int c = 0; c < NCLASS; ++c) {
        float v = hp[c];
        ps = fmaf(v, __ldg(&a2[c]), ps);
        pd = fmaf(v, __ldg(&a2[NCLASS + c]), pd);
    }
    g_s2src[n] = ps;
    g_s2dst[n] = pd;
}

// ---------------------------------------------------------------------------
// Layer-2 CSR aggregation: thread per (node, class); 2 nodes per warp.
// ---------------------------------------------------------------------------
__global__ __launch_bounds__(256) void k_agg2() {
    int t = blockIdx.x * blockDim.x + threadIdx.x;
    int n = t >> 4;
    int f = t & 15;
    if (n >= N_NODES) return;
    int beg = g_rowptr[n], end = g_rowptr[n + 1];
    float ss = g_s2src[n];
    float acc = 0.f, rs = 0.f;
    for (int i = beg; i < end; ++i) {
        int v = __ldg(&g_dst_sorted[i]);
        float lg = ss + __ldg(&g_s2dst[v]);
        lg = lg > 0.f ? lg : ALPHA * lg;
        float e = __expf(-lg);
        rs += e;
        acc = fmaf(e, __ldg(&g_h2[(size_t)v * NCLASS + f]), acc);
    }
    g_p2[(size_t)n * NCLASS + f] = acc / rs;
}

// ---------------------------------------------------------------------------
// elu + log_softmax over 16 classes, thread per node
// ---------------------------------------------------------------------------
__global__ void k_final(float* __restrict__ out) {
    int n = blockIdx.x * blockDim.x + threadIdx.x;
    if (n >= N_NODES) return;
    float v[NCLASS];
    float m = -1e30f;
#pragma unroll
    for (int c = 0; c < NCLASS; ++c) {
        float x = g_p2[(size_t)n * NCLASS + c];
        x = x > 0.f ? x : expm1f(x);
        v[c] = x;
        m = fmaxf(m, x);
    }
    float s = 0.f;
#pragma unroll
    for (int c = 0; c < NCLASS; ++c) s += __expf(v[c] - m);
    float l = m + logf(s);
#pragma unroll
    for (int c = 0; c < NCLASS; ++c) out[(size_t)n * NCLASS + c] = v[c] - l;
}

// ---------------------------------------------------------------------------
// Launch
// ---------------------------------------------------------------------------
extern "C" void kernel_launch(void* const* d_in, const int* in_sizes, int n_in,
                              void* d_out, int out_size) {
    const float* x  = (const float*)d_in[0];
    const int*   ei = (const int*)d_in[1];
    const float* W1 = (const float*)d_in[2];
    const float* a1 = (const float*)d_in[3];
    const float* W2 = (const float*)d_in[4];
    const float* a2 = (const float*)d_in[5];
    float* out = (float*)d_out;

    void *h1p = nullptr, *hcatp = nullptr, *h2p = nullptr;
    cudaGetSymbolAddress(&h1p, g_h1);
    cudaGetSymbolAddress(&hcatp, g_hcat);
    cudaGetSymbolAddress(&h2p, g_h2);

    // CSR build
    k_zero_deg<<<(N_NODES + 255) / 256, 256>>>();
    k_degree<<<(N_EDGES + 255) / 256, 256>>>(ei);
    k_scan<<<1, 1024>>>();
    k_scatter<<<(N_EDGES + 255) / 256, 256>>>(ei);

    // Layer 1: tf32 tensor-core GEMM
    dim3 g1((N_NODES + 127) / 128, H1);
    k_gemm1<<<g1, 256>>>(x, W1, (float*)h1p);
    dim3 gw((N_NODES + 7) / 8, H1);
    k_scores1<<<gw, 256>>>(a1);
    k_agg1<<<gw, 256>>>();

    // Layer 2
    dim3 g2((N_NODES + 63) / 64, 1);
    k_sgemm<<<g2, 256>>>((const float*)hcatp, W2, (float*)h2p, N_NODES, HCAT, NCLASS, 0, 0);
    k_scores2<<<(N_NODES + 255) / 256, 256>>>(a2);
    k_agg2<<<(N_NODES * NCLASS + 255) / 256, 256>>>();
    k_final<<<(N_NODES + 255) / 256, 256>>>(out);
}